// round 9
// baseline (speedup 1.0000x reference)
#include <cuda_runtime.h>
#include <cuda_bf16.h>
#include <cstdint>
#include <math.h>

// ---------------------------------------------------------------------------
// Attention B=8, L=2048, D=512 fp32 — bf16-split (3x mma.sync) HMMA pipeline.
// Round 9: single-barrier multistage mainloop (CUTLASS pattern): KC=32,
// 4 stages, wait_group 2, loads issued before compute. 256-thr CTAs,
// 2 CTAs/SM, block tile 128x64, warp tile 32x32.
// ---------------------------------------------------------------------------

#define BATCH 8
#define SEQ   2048
#define DIM   512
#define MTOT  (BATCH*SEQ)

#define BM     128
#define BN     64
#define KC     32
#define NTHR   256
#define STAGES 4

typedef __nv_bfloat16 bf16;

#define A_B   (BM*64)             // 8192  (128 rows x 32 bf16, 64B rows paired)
#define B_B   4096                // 64x32 (BMODE0) or 32x64 (BMODE1)
#define STAGE (2*A_B + 2*B_B)     // 24576
#define SMEM_TOTAL (STAGES*STAGE) // 98304 -> 2 CTAs/SM = 192KB

// ------------------------------ scratch ------------------------------------
__device__ bf16 g_in_hi[MTOT*DIM], g_in_lo[MTOT*DIM];
__device__ bf16 g_st_hi[MTOT*DIM], g_st_lo[MTOT*DIM];
__device__ bf16 g_wq_hi[DIM*DIM], g_wq_lo[DIM*DIM];
__device__ bf16 g_wk_hi[DIM*DIM], g_wk_lo[DIM*DIM];
__device__ bf16 g_wv_hi[DIM*DIM], g_wv_lo[DIM*DIM];
__device__ bf16 g_q_hi[MTOT*DIM], g_q_lo[MTOT*DIM];
__device__ bf16 g_k_hi[MTOT*DIM], g_k_lo[MTOT*DIM];
__device__ bf16 g_v_hi[MTOT*DIM], g_v_lo[MTOT*DIM];
__device__ float g_s[(size_t)BATCH*SEQ*SEQ];
__device__ bf16 g_p_hi[(size_t)BATCH*SEQ*SEQ], g_p_lo[(size_t)BATCH*SEQ*SEQ];

// ------------------------------ helpers ------------------------------------
__device__ __forceinline__ uint32_t smem_u32(const void* p) {
    uint32_t a;
    asm("{ .reg .u64 t; cvta.to.shared.u64 t, %1; cvt.u32.u64 %0, t; }" : "=r"(a) : "l"(p));
    return a;
}
#define SW128(o) ((o) ^ (((o) >> 3) & 0x70))
// 64B rows packed 2-per-128B-line, then SW128 (conflict-free for ldmatrix)
__device__ __forceinline__ uint32_t psw(int r, int kb) {
    return SW128((uint32_t)(((r >> 1) << 7) + ((r & 1) << 6) + kb));
}

__device__ __forceinline__ void cp16(uint32_t dst, const void* src) {
    asm volatile("cp.async.cg.shared.global [%0], [%1], 16;"
                 :: "r"(dst), "l"(__cvta_generic_to_global(src)) : "memory");
}
#define CP_COMMIT() asm volatile("cp.async.commit_group;" ::: "memory")

__device__ __forceinline__ void ldsm4(uint32_t* r, uint32_t addr) {
    asm volatile("ldmatrix.sync.aligned.m8n8.x4.shared.b16 {%0,%1,%2,%3}, [%4];"
                 : "=r"(r[0]), "=r"(r[1]), "=r"(r[2]), "=r"(r[3]) : "r"(addr));
}
__device__ __forceinline__ void ldsm4t(uint32_t* r, uint32_t addr) {
    asm volatile("ldmatrix.sync.aligned.m8n8.x4.trans.shared.b16 {%0,%1,%2,%3}, [%4];"
                 : "=r"(r[0]), "=r"(r[1]), "=r"(r[2]), "=r"(r[3]) : "r"(addr));
}
__device__ __forceinline__ void mma16816(float* c, const uint32_t* a,
                                         uint32_t b0, uint32_t b1) {
    asm volatile("mma.sync.aligned.m16n8k16.row.col.f32.bf16.bf16.f32 "
                 "{%0,%1,%2,%3}, {%4,%5,%6,%7}, {%8,%9}, {%0,%1,%2,%3};"
                 : "+f"(c[0]), "+f"(c[1]), "+f"(c[2]), "+f"(c[3])
                 : "r"(a[0]), "r"(a[1]), "r"(a[2]), "r"(a[3]), "r"(b0), "r"(b1));
}

// ------------------------------ split kernels ------------------------------
__device__ __forceinline__ void split4(const float4* src, __nv_bfloat162* hi,
                                       __nv_bfloat162* lo, int i) {
    float4 v = src[i];
    bf16 h0 = __float2bfloat16(v.x), h1 = __float2bfloat16(v.y);
    bf16 h2 = __float2bfloat16(v.z), h3 = __float2bfloat16(v.w);
    bf16 l0 = __float2bfloat16(v.x - __bfloat162float(h0));
    bf16 l1 = __float2bfloat16(v.y - __bfloat162float(h1));
    bf16 l2 = __float2bfloat16(v.z - __bfloat162float(h2));
    bf16 l3 = __float2bfloat16(v.w - __bfloat162float(h3));
    hi[2*i]   = __halves2bfloat162(h0, h1);
    hi[2*i+1] = __halves2bfloat162(h2, h3);
    lo[2*i]   = __halves2bfloat162(l0, l1);
    lo[2*i+1] = __halves2bfloat162(l2, l3);
}

__global__ void __launch_bounds__(256)
split_pair(const float4* s0, __nv_bfloat162* h0, __nv_bfloat162* l0,
           const float4* s1, __nv_bfloat162* h1, __nv_bfloat162* l1, int n4)
{
    int i = blockIdx.x * 256 + threadIdx.x;
    if (i >= n4) return;
    if (blockIdx.y == 0) split4(s0, h0, l0, i);
    else                 split4(s1, h1, l1, i);
}

__global__ void __launch_bounds__(256)
split_tri(const float4* s0, __nv_bfloat162* h0, __nv_bfloat162* l0,
          const float4* s1, __nv_bfloat162* h1, __nv_bfloat162* l1,
          const float4* s2, __nv_bfloat162* h2, __nv_bfloat162* l2, int n4)
{
    int i = blockIdx.x * 256 + threadIdx.x;
    if (i >= n4) return;
    if (blockIdx.y == 0)      split4(s0, h0, l0, i);
    else if (blockIdx.y == 1) split4(s1, h1, l1, i);
    else                      split4(s2, h2, l2, i);
}

// ------------------------------ GEMM core ----------------------------------
// 256 threads, 8 warps (4m x 2n), block tile 128x64, warp tile 32x32.
// Multistage: STAGES=4, one __syncthreads per chunk, loads issued pre-compute.
// BMODE 0: B is [N,K] K-major. BMODE 1: B is [K,N] N-major (trans ldmatrix).
// EPI 0: fp32*scale. EPI 1: +bias, split bf16 hi/lo.
template <int BMODE, int EPI>
__device__ __forceinline__ void gemm_core(
    const bf16* __restrict__ Ahi, const bf16* __restrict__ Alo,
    const bf16* __restrict__ Bhi, const bf16* __restrict__ Blo,
    const float* __restrict__ bias,
    float* __restrict__ Cf, bf16* __restrict__ Chi, bf16* __restrict__ Clo,
    int N, int K, float scale, int m0, int n0, char* smem)
{
    const uint32_t sb = smem_u32(smem);
    const int tid = threadIdx.x, lane = tid & 31, wid = tid >> 5;
    const int wm = wid & 3, wn = wid >> 2;    // 4(m) x 2(n)
    const int ldB = BMODE ? N : K;
    const int nch = K / KC;

    // issue chunk i (or an empty commit group past the end)
    auto issue = [&](int i) {
        if (i < nch) {
            const int k0 = i * KC;
            const uint32_t st = sb + (i % STAGES) * STAGE;
            // A hi/lo: 128 rows x 32 bf16 (4 x 16B chunks per row)
            #pragma unroll
            for (int u = 0; u < 2; u++) {
                int idx = tid + u * NTHR;      // 0..511
                int r = idx >> 2, c = idx & 3;
                uint32_t off = psw(r, c * 16);
                cp16(st + off,       Ahi + (long)(m0 + r) * K + k0 + c * 8);
                cp16(st + A_B + off, Alo + (long)(m0 + r) * K + k0 + c * 8);
            }
            const uint32_t bst = st + 2 * A_B;
            if (BMODE == 0) {
                // B: 64 rows (n) x 32 bf16 (k): 64x4 = 256 chunks
                int r = tid >> 2, c = tid & 3;
                uint32_t off = psw(r, c * 16);
                cp16(bst + off,       Bhi + (long)(n0 + r) * ldB + k0 + c * 8);
                cp16(bst + B_B + off, Blo + (long)(n0 + r) * ldB + k0 + c * 8);
            } else {
                // B: 32 rows (k) x 64 bf16 (n): 32x8 = 256 chunks, 128B rows
                int kk = tid >> 3, nc = tid & 7;
                uint32_t off = SW128((uint32_t)(kk * 128 + nc * 16));
                cp16(bst + off,       Bhi + (long)(k0 + kk) * ldB + n0 + nc * 8);
                cp16(bst + B_B + off, Blo + (long)(k0 + kk) * ldB + n0 + nc * 8);
            }
        }
        CP_COMMIT();
    };

    float acc[2][4][4];
    #pragma unroll
    for (int a = 0; a < 2; a++)
        #pragma unroll
        for (int b = 0; b < 4; b++)
            #pragma unroll
            for (int c = 0; c < 4; c++) acc[a][b][c] = 0.f;

    issue(0); issue(1); issue(2);

    for (int i = 0; i < nch; i++) {
        asm volatile("cp.async.wait_group 2;" ::: "memory");  // chunk i landed
        __syncthreads();           // publish chunk i; all warps done with i-1
        issue(i + STAGES - 1);     // refill (i-1)%4 buffer; empty group at tail

        const uint32_t st = sb + (i % STAGES) * STAGE;
        const uint32_t sAhi = st, sAlo = st + A_B;
        const uint32_t sBhi = st + 2 * A_B, sBlo = st + 2 * A_B + B_B;

        #pragma unroll
        for (int ks = 0; ks < 2; ks++) {      // KC=32 -> 2 k-steps of 16
            uint32_t ah[2][4], al[2][4];
            #pragma unroll
            for (int mc = 0; mc < 2; mc++) {
                int row = wm * 32 + mc * 16 + (lane & 15);
                int kb  = ks * 32 + (lane >> 4) * 16;
                uint32_t off = psw(row, kb);
                ldsm4(ah[mc], sAhi + off);
                ldsm4(al[mc], sAlo + off);
            }
            #pragma unroll
            for (int p = 0; p < 2; p++) {
                uint32_t bh[4], bl[4];
                if (BMODE == 0) {
                    int row = wn * 32 + p * 16 + ((lane >> 4) & 1) * 8 + (lane & 7);
                    int kb  = ks * 32 + ((lane >> 3) & 1) * 16;
                    uint32_t off = psw(row, kb);
                    ldsm4(bh, sBhi + off);
                    ldsm4(bl, sBlo + off);
                } else {
                    int kk   = ks * 16 + ((lane >> 3) & 1) * 8 + (lane & 7);
                    int ncol = wn * 32 + p * 16 + ((lane >> 4) & 1) * 8;
                    uint32_t off = SW128((uint32_t)(kk * 128 + ncol * 2));
                    ldsm4t(bh, sBhi + off);
                    ldsm4t(bl, sBlo + off);
                }
                #pragma unroll
                for (int mc = 0; mc < 2; mc++)
                    #pragma unroll
                    for (int s = 0; s < 2; s++) {
                        float* a = acc[mc][p * 2 + s];
                        mma16816(a, ah[mc], bh[s*2], bh[s*2+1]);   // hi*hi
                        mma16816(a, ah[mc], bl[s*2], bl[s*2+1]);   // hi*lo
                        mma16816(a, al[mc], bh[s*2], bh[s*2+1]);   // lo*hi
                    }
            }
        }
    }

    // ---- epilogue: warp covers rows wm*32..+31, cols wn*32..+31 ----
    const int g = lane >> 2, tig = lane & 3;
    #pragma unroll
    for (int mc = 0; mc < 2; mc++) {
        int row = m0 + wm * 32 + mc * 16 + g;
        #pragma unroll
        for (int ng = 0; ng < 4; ng++) {
            int col = n0 + wn * 32 + ng * 8 + tig * 2;
            float c0 = acc[mc][ng][0], c1 = acc[mc][ng][1];
            float c2 = acc[mc][ng][2], c3 = acc[mc][ng][3];
            if (EPI == 0) {
                *(float2*)(Cf + (long)row * N + col)       = make_float2(c0 * scale, c1 * scale);
                *(float2*)(Cf + (long)(row + 8) * N + col) = make_float2(c2 * scale, c3 * scale);
            } else {
                float b0 = bias[col], b1 = bias[col + 1];
                float v0 = c0 + b0, v1 = c1 + b1;
                float v2 = c2 + b0, v3 = c3 + b1;
                bf16 h0 = __float2bfloat16(v0), h1 = __float2bfloat16(v1);
                bf16 h2 = __float2bfloat16(v2), h3 = __float2bfloat16(v3);
                bf16 l0 = __float2bfloat16(v0 - __bfloat162float(h0));
                bf16 l1 = __float2bfloat16(v1 - __bfloat162float(h1));
                bf16 l2 = __float2bfloat16(v2 - __bfloat162float(h2));
                bf16 l3 = __float2bfloat16(v3 - __bfloat162float(h3));
                long o0 = (long)row * N + col, o1 = (long)(row + 8) * N + col;
                *(__nv_bfloat162*)(Chi + o0) = __halves2bfloat162(h0, h1);
                *(__nv_bfloat162*)(Chi + o1) = __halves2bfloat162(h2, h3);
                *(__nv_bfloat162*)(Clo + o0) = __halves2bfloat162(l0, l1);
                *(__nv_bfloat162*)(Clo + o1) = __halves2bfloat162(l2, l3);
            }
        }
    }
}

// ---- fused QKV: blockIdx.z selects projection ----
__global__ void __launch_bounds__(NTHR, 2)
gemm_qkv(const bf16* in_hi, const bf16* in_lo,
         const bf16* st_hi, const bf16* st_lo,
         const bf16* wq_hi, const bf16* wq_lo, const float* bq,
         const bf16* wk_hi, const bf16* wk_lo, const float* bk,
         const bf16* wv_hi, const bf16* wv_lo, const float* bv,
         bf16* q_hi, bf16* q_lo, bf16* k_hi, bf16* k_lo,
         bf16* v_hi, bf16* v_lo)
{
    extern __shared__ char smem[];
    const int z = blockIdx.z;
    const bf16 *Ahi, *Alo, *Bhi, *Blo;
    const float* bias;
    bf16 *Chi, *Clo;
    if (z == 0)      { Ahi = in_hi; Alo = in_lo; Bhi = wq_hi; Blo = wq_lo; bias = bq; Chi = q_hi; Clo = q_lo; }
    else if (z == 1) { Ahi = st_hi; Alo = st_lo; Bhi = wk_hi; Blo = wk_lo; bias = bk; Chi = k_hi; Clo = k_lo; }
    else             { Ahi = st_hi; Alo = st_lo; Bhi = wv_hi; Blo = wv_lo; bias = bv; Chi = v_hi; Clo = v_lo; }
    gemm_core<0, 1>(Ahi, Alo, Bhi, Blo, bias, nullptr, Chi, Clo,
                    DIM, DIM, 1.f, blockIdx.y * BM, blockIdx.x * BN, smem);
}

// ---- batched GEMM (scores / PV), blockIdx.z = batch ----
template <int BMODE>
__global__ void __launch_bounds__(NTHR, 2)
gemm_batch(const bf16* __restrict__ Ahi_, const bf16* __restrict__ Alo_,
           const bf16* __restrict__ Bhi_, const bf16* __restrict__ Blo_,
           float* __restrict__ Cf, int N, int K,
           long sA, long sB, long sC, float scale)
{
    extern __shared__ char smem[];
    const int z = blockIdx.z;
    gemm_core<BMODE, 0>(Ahi_ + (long)z * sA, Alo_ + (long)z * sA,
                        Bhi_ + (long)z * sB, Blo_ + (long)z * sB,
                        nullptr, Cf + (long)z * sC, nullptr, nullptr,
                        N, K, scale, blockIdx.y * BM, blockIdx.x * BN, smem);
}

// ------------------------------ softmax ------------------------------------
__global__ void __launch_bounds__(256)
softmax_mask(const float* __restrict__ S, const int* __restrict__ mask,
             bf16* __restrict__ Phi, bf16* __restrict__ Plo)
{
    const size_t base = (size_t)blockIdx.x * SEQ;
    const float4* rowv = (const float4*)(S + base);
    const int4*   mv   = (const int4*)(mask + base);
    const int tid = threadIdx.x;

    __shared__ float red[8];

    float v[8];
    float mx = -INFINITY;
    #pragma unroll
    for (int j = 0; j < 2; j++) {
        int idx = tid + j * 256;
        float4 sv = rowv[idx];
        int4   mm = mv[idx];
        float* vp = v + j * 4;
        vp[0] = (mm.x == 0) ? -INFINITY : sv.x;
        vp[1] = (mm.y == 0) ? -INFINITY : sv.y;
        vp[2] = (mm.z == 0) ? -INFINITY : sv.z;
        vp[3] = (mm.w == 0) ? -INFINITY : sv.w;
        mx = fmaxf(mx, fmaxf(fmaxf(vp[0], vp[1]), fmaxf(vp[2], vp[3])));
    }
    #pragma unroll
    for (int o = 16; o > 0; o >>= 1) mx = fmaxf(mx, __shfl_xor_sync(0xffffffffu, mx, o));
    if ((tid & 31) == 0) red[tid >> 5] = mx;
    __syncthreads();
    mx = red[0];
    #pragma unroll
    for (int w = 1; w < 8; w++) mx = fmaxf(mx, red[w]);
    __syncthreads();

    float sum = 0.f;
    #pragma unroll
    for (int i = 0; i < 8; i++) { v[i] = __expf(v[i] - mx); sum += v[i]; }
    #pragma unroll
    for (int o = 16; o > 0; o >>= 1) sum += __shfl_xor_sync(0xffffffffu, sum, o);
    if ((tid & 31) == 0) red[tid >> 5] = sum;
    __syncthreads();
    float total = 0.f;
    #pragma unroll
    for (int w = 0; w < 8; w++) total += red[w];

    const float inv = 1.f / total;
    #pragma unroll
    for (int j = 0; j < 2; j++) {
        int idx = tid + j * 256;
        float p0 = v[j*4+0] * inv, p1 = v[j*4+1] * inv;
        float p2 = v[j*4+2] * inv, p3 = v[j*4+3] * inv;
        bf16 h0 = __float2bfloat16(p0), h1 = __float2bfloat16(p1);
        bf16 h2 = __float2bfloat16(p2), h3 = __float2bfloat16(p3);
        bf16 l0 = __float2bfloat16(p0 - __bfloat162float(h0));
        bf16 l1 = __float2bfloat16(p1 - __bfloat162float(h1));
        bf16 l2 = __float2bfloat16(p2 - __bfloat162float(h2));
        bf16 l3 = __float2bfloat16(p3 - __bfloat162float(h3));
        __nv_bfloat162* ph = (__nv_bfloat162*)(Phi + base + idx * 4);
        __nv_bfloat162* pl = (__nv_bfloat162*)(Plo + base + idx * 4);
        ph[0] = __halves2bfloat162(h0, h1);
        ph[1] = __halves2bfloat162(h2, h3);
        pl[0] = __halves2bfloat162(l0, l1);
        pl[1] = __halves2bfloat162(l2, l3);
    }
}

// ------------------------------ launch -------------------------------------
extern "C" void kernel_launch(void* const* d_in, const int* in_sizes, int n_in,
                              void* d_out, int out_size)
{
    const float* input  = (const float*)d_in[0];
    const float* states = (const float*)d_in[1];
    const int*   mask   = (const int*)d_in[2];
    const float* wq     = (const float*)d_in[3];
    const float* bq     = (const float*)d_in[4];
    const float* wk     = (const float*)d_in[5];
    const float* bk     = (const float*)d_in[6];
    const float* wv     = (const float*)d_in[7];
    const float* bv     = (const float*)d_in[8];
    float* out = (float*)d_out;

    cudaFuncSetAttribute(gemm_qkv,      cudaFuncAttributeMaxDynamicSharedMemorySize, SMEM_TOTAL);
    cudaFuncSetAttribute(gemm_batch<0>, cudaFuncAttributeMaxDynamicSharedMemorySize, SMEM_TOTAL);
    cudaFuncSetAttribute(gemm_batch<1>, cudaFuncAttributeMaxDynamicSharedMemorySize, SMEM_TOTAL);

    bf16 *in_hi, *in_lo, *st_hi, *st_lo;
    bf16 *wq_hi, *wq_lo, *wk_hi, *wk_lo, *wv_hi, *wv_lo;
    bf16 *q_hi, *q_lo, *k_hi, *k_lo, *v_hi, *v_lo, *p_hi, *p_lo;
    float* s;
    cudaGetSymbolAddress((void**)&in_hi, g_in_hi);  cudaGetSymbolAddress((void**)&in_lo, g_in_lo);
    cudaGetSymbolAddress((void**)&st_hi, g_st_hi);  cudaGetSymbolAddress((void**)&st_lo, g_st_lo);
    cudaGetSymbolAddress((void**)&wq_hi, g_wq_hi);  cudaGetSymbolAddress((void**)&wq_lo, g_wq_lo);
    cudaGetSymbolAddress((void**)&wk_hi, g_wk_hi);  cudaGetSymbolAddress((void**)&wk_lo, g_wk_lo);
    cudaGetSymbolAddress((void**)&wv_hi, g_wv_hi);  cudaGetSymbolAddress((void**)&wv_lo, g_wv_lo);
    cudaGetSymbolAddress((void**)&q_hi,  g_q_hi);   cudaGetSymbolAddress((void**)&q_lo,  g_q_lo);
    cudaGetSymbolAddress((void**)&k_hi,  g_k_hi);   cudaGetSymbolAddress((void**)&k_lo,  g_k_lo);
    cudaGetSymbolAddress((void**)&v_hi,  g_v_hi);   cudaGetSymbolAddress((void**)&v_lo,  g_v_lo);
    cudaGetSymbolAddress((void**)&p_hi,  g_p_hi);   cudaGetSymbolAddress((void**)&p_lo,  g_p_lo);
    cudaGetSymbolAddress((void**)&s, g_s);

    const float scale = 1.0f / sqrtf((float)DIM);
    const long sQK = (long)SEQ * DIM;
    const long sS  = (long)SEQ * SEQ;

    // splits (fp32 -> bf16 hi/lo)
    {
        int n4 = MTOT * DIM / 4;
        split_pair<<<dim3((n4 + 255) / 256, 2), 256>>>(
            (const float4*)input,  (__nv_bfloat162*)in_hi, (__nv_bfloat162*)in_lo,
            (const float4*)states, (__nv_bfloat162*)st_hi, (__nv_bfloat162*)st_lo, n4);
        int w4 = DIM * DIM / 4;
        split_tri<<<dim3((w4 + 255) / 256, 3), 256>>>(
            (const float4*)wq, (__nv_bfloat162*)wq_hi, (__nv_bfloat162*)wq_lo,
            (const float4*)wk, (__nv_bfloat162*)wk_hi, (__nv_bfloat162*)wk_lo,
            (const float4*)wv, (__nv_bfloat162*)wv_hi, (__nv_bfloat162*)wv_lo, w4);
    }

    // fused QKV: [16384,512] = A @ W^T + b, z = projection
    gemm_qkv<<<dim3(DIM / BN, MTOT / BM, 3), NTHR, SMEM_TOTAL>>>(
        in_hi, in_lo, st_hi, st_lo,
        wq_hi, wq_lo, bq, wk_hi, wk_lo, bk, wv_hi, wv_lo, bv,
        q_hi, q_lo, k_hi, k_lo, v_hi, v_lo);

    // scores: per-batch [2048,2048] = q @ k^T * scale
    gemm_batch<0><<<dim3(SEQ / BN, SEQ / BM, BATCH), NTHR, SMEM_TOTAL>>>(
        q_hi, q_lo, k_hi, k_lo, s, SEQ, DIM, sQK, sQK, sS, scale);

    // masked softmax -> P hi/lo bf16
    softmax_mask<<<BATCH * SEQ, 256>>>(s, mask, p_hi, p_lo);

    // context: per-batch [2048,512] = P @ V  (V [2048,512] N-major, trans)
    gemm_batch<1><<<dim3(DIM / BN, SEQ / BM, BATCH), NTHR, SMEM_TOTAL>>>(
        p_hi, p_lo, v_hi, v_lo, out, DIM, SEQ, sS, sQK, sQK, 1.f);
}

// round 12
// speedup vs baseline: 1.0595x; 1.0595x over previous
#include <cuda_runtime.h>
#include <cuda_bf16.h>
#include <cstdint>
#include <math.h>

// ---------------------------------------------------------------------------
// Attention B=8, L=2048, D=512 fp32 — bf16-split (3x mma.sync) HMMA pipeline.
// Round 11 (resubmit of round 10; prior run died to container flake):
// scores keeps the round-8 core (best measured: 268us, tensor 74.5%);
// QKV + PV use a 64x64-tile, KC=64, 3-stage single-barrier multistage core
// (wave-tail fix: PV eff 0.87->0.989, QKV 0.94->0.996).
// ---------------------------------------------------------------------------

#define BATCH 8
#define SEQ   2048
#define DIM   512
#define MTOT  (BATCH*SEQ)

#define KC   64
#define NTHR 256

typedef __nv_bfloat16 bf16;

// round-8 core (scores): tile 128x64, 2 stages
#define BM1   128
#define BN1   64
#define A_B1  (BM1*128)             // 16384
#define B_B1  (BN1*128)             // 8192
#define STAGE1 (2*A_B1 + 2*B_B1)    // 49152
#define SMEM1  (2*STAGE1)           // 98304

// multistage core (QKV/PV): tile 64x64, 3 stages
#define BM2   64
#define BN2   64
#define A_B2  (BM2*128)             // 8192
#define B_B2  (BN2*128)             // 8192
#define STAGE2 (2*A_B2 + 2*B_B2)    // 32768
#define SMEM2  (3*STAGE2)           // 98304

// ------------------------------ scratch ------------------------------------
__device__ bf16 g_in_hi[MTOT*DIM], g_in_lo[MTOT*DIM];
__device__ bf16 g_st_hi[MTOT*DIM], g_st_lo[MTOT*DIM];
__device__ bf16 g_wq_hi[DIM*DIM], g_wq_lo[DIM*DIM];
__device__ bf16 g_wk_hi[DIM*DIM], g_wk_lo[DIM*DIM];
__device__ bf16 g_wv_hi[DIM*DIM], g_wv_lo[DIM*DIM];
__device__ bf16 g_q_hi[MTOT*DIM], g_q_lo[MTOT*DIM];
__device__ bf16 g_k_hi[MTOT*DIM], g_k_lo[MTOT*DIM];
__device__ bf16 g_v_hi[MTOT*DIM], g_v_lo[MTOT*DIM];
__device__ float g_s[(size_t)BATCH*SEQ*SEQ];
__device__ bf16 g_p_hi[(size_t)BATCH*SEQ*SEQ], g_p_lo[(size_t)BATCH*SEQ*SEQ];

// ------------------------------ helpers ------------------------------------
__device__ __forceinline__ uint32_t smem_u32(const void* p) {
    uint32_t a;
    asm("{ .reg .u64 t; cvta.to.shared.u64 t, %1; cvt.u32.u64 %0, t; }" : "=r"(a) : "l"(p));
    return a;
}
#define SW128(o) ((o) ^ (((o) >> 3) & 0x70))

__device__ __forceinline__ void cp16(uint32_t dst, const void* src) {
    asm volatile("cp.async.cg.shared.global [%0], [%1], 16;"
                 :: "r"(dst), "l"(__cvta_generic_to_global(src)) : "memory");
}
#define CP_COMMIT() asm volatile("cp.async.commit_group;" ::: "memory")

__device__ __forceinline__ void ldsm4(uint32_t* r, uint32_t addr) {
    asm volatile("ldmatrix.sync.aligned.m8n8.x4.shared.b16 {%0,%1,%2,%3}, [%4];"
                 : "=r"(r[0]), "=r"(r[1]), "=r"(r[2]), "=r"(r[3]) : "r"(addr));
}
__device__ __forceinline__ void ldsm4t(uint32_t* r, uint32_t addr) {
    asm volatile("ldmatrix.sync.aligned.m8n8.x4.trans.shared.b16 {%0,%1,%2,%3}, [%4];"
                 : "=r"(r[0]), "=r"(r[1]), "=r"(r[2]), "=r"(r[3]) : "r"(addr));
}
__device__ __forceinline__ void mma16816(float* c, const uint32_t* a,
                                         uint32_t b0, uint32_t b1) {
    asm volatile("mma.sync.aligned.m16n8k16.row.col.f32.bf16.bf16.f32 "
                 "{%0,%1,%2,%3}, {%4,%5,%6,%7}, {%8,%9}, {%0,%1,%2,%3};"
                 : "+f"(c[0]), "+f"(c[1]), "+f"(c[2]), "+f"(c[3])
                 : "r"(a[0]), "r"(a[1]), "r"(a[2]), "r"(a[3]), "r"(b0), "r"(b1));
}

// ------------------------------ split kernels ------------------------------
__device__ __forceinline__ void split4(const float4* src, __nv_bfloat162* hi,
                                       __nv_bfloat162* lo, int i) {
    float4 v = src[i];
    bf16 h0 = __float2bfloat16(v.x), h1 = __float2bfloat16(v.y);
    bf16 h2 = __float2bfloat16(v.z), h3 = __float2bfloat16(v.w);
    bf16 l0 = __float2bfloat16(v.x - __bfloat162float(h0));
    bf16 l1 = __float2bfloat16(v.y - __bfloat162float(h1));
    bf16 l2 = __float2bfloat16(v.z - __bfloat162float(h2));
    bf16 l3 = __float2bfloat16(v.w - __bfloat162float(h3));
    hi[2*i]   = __halves2bfloat162(h0, h1);
    hi[2*i+1] = __halves2bfloat162(h2, h3);
    lo[2*i]   = __halves2bfloat162(l0, l1);
    lo[2*i+1] = __halves2bfloat162(l2, l3);
}

__global__ void __launch_bounds__(256)
split_pair(const float4* s0, __nv_bfloat162* h0, __nv_bfloat162* l0,
           const float4* s1, __nv_bfloat162* h1, __nv_bfloat162* l1, int n4)
{
    int i = blockIdx.x * 256 + threadIdx.x;
    if (i >= n4) return;
    if (blockIdx.y == 0) split4(s0, h0, l0, i);
    else                 split4(s1, h1, l1, i);
}

__global__ void __launch_bounds__(256)
split_tri(const float4* s0, __nv_bfloat162* h0, __nv_bfloat162* l0,
          const float4* s1, __nv_bfloat162* h1, __nv_bfloat162* l1,
          const float4* s2, __nv_bfloat162* h2, __nv_bfloat162* l2, int n4)
{
    int i = blockIdx.x * 256 + threadIdx.x;
    if (i >= n4) return;
    if (blockIdx.y == 0)      split4(s0, h0, l0, i);
    else if (blockIdx.y == 1) split4(s1, h1, l1, i);
    else                      split4(s2, h2, l2, i);
}

// ===================== core A: round-8 (scores) ============================
// 256 thr, 8 warps (4m x 2n), tile 128x64, 2-stage KC=64, BMODE0, EPI0.
__device__ __forceinline__ void gemm_core_r8(
    const bf16* __restrict__ Ahi, const bf16* __restrict__ Alo,
    const bf16* __restrict__ Bhi, const bf16* __restrict__ Blo,
    float* __restrict__ Cf,
    int N, int K, float scale, int m0, int n0, char* smem)
{
    const uint32_t sb = smem_u32(smem);
    const int tid = threadIdx.x, lane = tid & 31, wid = tid >> 5;
    const int wm = wid & 3, wn = wid >> 2;
    const int nch = K / KC;

    auto issue = [&](int i) {
        const int k0 = i * KC;
        const uint32_t st = sb + (i & 1) * STAGE1;
        #pragma unroll
        for (int u = 0; u < 4; u++) {
            int idx = tid + u * NTHR;
            int r = idx >> 3, c = idx & 7;
            uint32_t off = SW128((uint32_t)(r * 128 + c * 16));
            cp16(st + off,        Ahi + (long)(m0 + r) * K + k0 + c * 8);
            cp16(st + A_B1 + off, Alo + (long)(m0 + r) * K + k0 + c * 8);
        }
        const uint32_t bst = st + 2 * A_B1;
        #pragma unroll
        for (int u = 0; u < 2; u++) {
            int idx = tid + u * NTHR;
            int r = idx >> 3, c = idx & 7;
            uint32_t off = SW128((uint32_t)(r * 128 + c * 16));
            cp16(bst + off,        Bhi + (long)(n0 + r) * K + k0 + c * 8);
            cp16(bst + B_B1 + off, Blo + (long)(n0 + r) * K + k0 + c * 8);
        }
        CP_COMMIT();
    };

    float acc[2][4][4];
    #pragma unroll
    for (int a = 0; a < 2; a++)
        #pragma unroll
        for (int b = 0; b < 4; b++)
            #pragma unroll
            for (int c = 0; c < 4; c++) acc[a][b][c] = 0.f;

    issue(0); issue(1);

    for (int i = 0; i < nch; i++) {
        if (i < nch - 1) asm volatile("cp.async.wait_group 1;" ::: "memory");
        else             asm volatile("cp.async.wait_group 0;" ::: "memory");
        __syncthreads();

        const uint32_t st = sb + (i & 1) * STAGE1;
        const uint32_t sAhi = st, sAlo = st + A_B1;
        const uint32_t sBhi = st + 2 * A_B1, sBlo = st + 2 * A_B1 + B_B1;

        #pragma unroll
        for (int ks = 0; ks < 4; ks++) {
            uint32_t ah[2][4], al[2][4];
            #pragma unroll
            for (int mc = 0; mc < 2; mc++) {
                int row = wm * 32 + mc * 16 + (lane & 15);
                int kb  = ks * 32 + (lane >> 4) * 16;
                uint32_t off = SW128((uint32_t)(row * 128 + kb));
                ldsm4(ah[mc], sAhi + off);
                ldsm4(al[mc], sAlo + off);
            }
            #pragma unroll
            for (int p = 0; p < 2; p++) {
                uint32_t bh[4], bl[4];
                int row = wn * 32 + p * 16 + ((lane >> 4) & 1) * 8 + (lane & 7);
                int kb  = ks * 32 + ((lane >> 3) & 1) * 16;
                uint32_t off = SW128((uint32_t)(row * 128 + kb));
                ldsm4(bh, sBhi + off);
                ldsm4(bl, sBlo + off);
                #pragma unroll
                for (int mc = 0; mc < 2; mc++)
                    #pragma unroll
                    for (int s = 0; s < 2; s++) {
                        float* a = acc[mc][p * 2 + s];
                        mma16816(a, ah[mc], bh[s*2], bh[s*2+1]);
                        mma16816(a, ah[mc], bl[s*2], bl[s*2+1]);
                        mma16816(a, al[mc], bh[s*2], bh[s*2+1]);
                    }
            }
        }
        __syncthreads();
        if (i + 2 < nch) issue(i + 2);
    }

    const int g = lane >> 2, tig = lane & 3;
    #pragma unroll
    for (int mc = 0; mc < 2; mc++) {
        int row = m0 + wm * 32 + mc * 16 + g;
        #pragma unroll
        for (int ng = 0; ng < 4; ng++) {
            int col = n0 + wn * 32 + ng * 8 + tig * 2;
            *(float2*)(Cf + (long)row * N + col) =
                make_float2(acc[mc][ng][0] * scale, acc[mc][ng][1] * scale);
            *(float2*)(Cf + (long)(row + 8) * N + col) =
                make_float2(acc[mc][ng][2] * scale, acc[mc][ng][3] * scale);
        }
    }
}

// ===================== core B: multistage 64x64 (QKV/PV) ===================
// 256 thr, 8 warps (2m x 4n), tile 64x64, warp tile 32x16, 3-stage KC=64,
// single __syncthreads per chunk, loads issued before compute.
// BMODE 0: B [N,K] K-major. BMODE 1: B [K,N] N-major (trans ldmatrix).
// EPI 0: fp32*scale. EPI 1: +bias, split bf16 hi/lo.
template <int BMODE, int EPI>
__device__ __forceinline__ void gemm_core_ms(
    const bf16* __restrict__ Ahi, const bf16* __restrict__ Alo,
    const bf16* __restrict__ Bhi, const bf16* __restrict__ Blo,
    const float* __restrict__ bias,
    float* __restrict__ Cf, bf16* __restrict__ Chi, bf16* __restrict__ Clo,
    int N, int K, float scale, int m0, int n0, char* smem)
{
    const uint32_t sb = smem_u32(smem);
    const int tid = threadIdx.x, lane = tid & 31, wid = tid >> 5;
    const int wm = wid & 1, wn = wid >> 1;    // 2(m) x 4(n)
    const int ldB = BMODE ? N : K;
    const int nch = K / KC;

    auto issue = [&](int i) {
        if (i < nch) {
            const int k0 = i * KC;
            const uint32_t st = sb + (i % 3) * STAGE2;
            #pragma unroll
            for (int u = 0; u < 2; u++) {
                int idx = tid + u * NTHR;      // 0..511 (64 rows x 8 chunks)
                int r = idx >> 3, c = idx & 7;
                uint32_t off = SW128((uint32_t)(r * 128 + c * 16));
                cp16(st + off,        Ahi + (long)(m0 + r) * K + k0 + c * 8);
                cp16(st + A_B2 + off, Alo + (long)(m0 + r) * K + k0 + c * 8);
            }
            const uint32_t bst = st + 2 * A_B2;
            #pragma unroll
            for (int u = 0; u < 2; u++) {
                int idx = tid + u * NTHR;
                int r = idx >> 3, c = idx & 7;
                uint32_t off = SW128((uint32_t)(r * 128 + c * 16));
                const bf16 *ph, *pl;
                if (BMODE == 0) {
                    ph = Bhi + (long)(n0 + r) * ldB + k0 + c * 8;
                    pl = Blo + (long)(n0 + r) * ldB + k0 + c * 8;
                } else {
                    ph = Bhi + (long)(k0 + r) * ldB + n0 + c * 8;
                    pl = Blo + (long)(k0 + r) * ldB + n0 + c * 8;
                }
                cp16(bst + off,        ph);
                cp16(bst + B_B2 + off, pl);
            }
        }
        CP_COMMIT();
    };

    float acc[2][2][4];
    #pragma unroll
    for (int a = 0; a < 2; a++)
        #pragma unroll
        for (int b = 0; b < 2; b++)
            #pragma unroll
            for (int c = 0; c < 4; c++) acc[a][b][c] = 0.f;

    issue(0); issue(1);

    for (int i = 0; i < nch; i++) {
        asm volatile("cp.async.wait_group 1;" ::: "memory");  // chunk i landed
        __syncthreads();          // all warps done with chunk i-1's buffer
        issue(i + 2);             // refill (i-1)%3 buffer (empty group at tail)

        const uint32_t st = sb + (i % 3) * STAGE2;
        const uint32_t sAhi = st, sAlo = st + A_B2;
        const uint32_t sBhi = st + 2 * A_B2, sBlo = st + 2 * A_B2 + B_B2;

        #pragma unroll
        for (int ks = 0; ks < 4; ks++) {
            uint32_t ah[2][4], al[2][4], bh[4], bl[4];
            #pragma unroll
            for (int mc = 0; mc < 2; mc++) {
                int row = wm * 32 + mc * 16 + (lane & 15);
                int kb  = ks * 32 + (lane >> 4) * 16;
                uint32_t off = SW128((uint32_t)(row * 128 + kb));
                ldsm4(ah[mc], sAhi + off);
                ldsm4(al[mc], sAlo + off);
            }
            if (BMODE == 0) {
                int row = wn * 16 + ((lane >> 4) & 1) * 8 + (lane & 7);
                int kb  = ks * 32 + ((lane >> 3) & 1) * 16;
                uint32_t off = SW128((uint32_t)(row * 128 + kb));
                ldsm4(bh, sBhi + off);
                ldsm4(bl, sBlo + off);
            } else {
                int kk   = ks * 16 + ((lane >> 3) & 1) * 8 + (lane & 7);
                int ncol = wn * 16 + ((lane >> 4) & 1) * 8;
                uint32_t off = SW128((uint32_t)(kk * 128 + ncol * 2));
                ldsm4t(bh, sBhi + off);
                ldsm4t(bl, sBlo + off);
            }
            #pragma unroll
            for (int mc = 0; mc < 2; mc++)
                #pragma unroll
                for (int s = 0; s < 2; s++) {
                    float* a = acc[mc][s];
                    mma16816(a, ah[mc], bh[s*2], bh[s*2+1]);   // hi*hi
                    mma16816(a, ah[mc], bl[s*2], bl[s*2+1]);   // hi*lo
                    mma16816(a, al[mc], bh[s*2], bh[s*2+1]);   // lo*hi
                }
        }
    }

    // ---- epilogue: warp covers rows wm*32..+31, cols wn*16..+15 ----
    const int g = lane >> 2, tig = lane & 3;
    #pragma unroll
    for (int mc = 0; mc < 2; mc++) {
        int row = m0 + wm * 32 + mc * 16 + g;
        #pragma unroll
        for (int ng = 0; ng < 2; ng++) {
            int col = n0 + wn * 16 + ng * 8 + tig * 2;
            float c0 = acc[mc][ng][0], c1 = acc[mc][ng][1];
            float c2 = acc[mc][ng][2], c3 = acc[mc][ng][3];
            if (EPI == 0) {
                *(float2*)(Cf + (long)row * N + col)       = make_float2(c0 * scale, c1 * scale);
                *(float2*)(Cf + (long)(row + 8) * N + col) = make_float2(c2 * scale, c3 * scale);
            } else {
                float b0 = bias[col], b1 = bias[col + 1];
                float v0 = c0 + b0, v1 = c1 + b1;
                float v2 = c2 + b0, v3 = c3 + b1;
                bf16 h0 = __float2bfloat16(v0), h1 = __float2bfloat16(v1);
                bf16 h2 = __float2bfloat16(v2), h3 = __float2bfloat16(v3);
                bf16 l0 = __float2bfloat16(v0 - __bfloat162float(h0));
                bf16 l1 = __float2bfloat16(v1 - __bfloat162float(h1));
                bf16 l2 = __float2bfloat16(v2 - __bfloat162float(h2));
                bf16 l3 = __float2bfloat16(v3 - __bfloat162float(h3));
                long o0 = (long)row * N + col, o1 = (long)(row + 8) * N + col;
                *(__nv_bfloat162*)(Chi + o0) = __halves2bfloat162(h0, h1);
                *(__nv_bfloat162*)(Chi + o1) = __halves2bfloat162(h2, h3);
                *(__nv_bfloat162*)(Clo + o0) = __halves2bfloat162(l0, l1);
                *(__nv_bfloat162*)(Clo + o1) = __halves2bfloat162(l2, l3);
            }
        }
    }
}

// ---- kernels ----
__global__ void __launch_bounds__(NTHR, 2)
gemm_scores(const bf16* __restrict__ q_hi, const bf16* __restrict__ q_lo,
            const bf16* __restrict__ k_hi, const bf16* __restrict__ k_lo,
            float* __restrict__ s, float scale)
{
    extern __shared__ char smem[];
    const long z = blockIdx.z;
    gemm_core_r8(q_hi + z * SEQ * DIM, q_lo + z * SEQ * DIM,
                 k_hi + z * SEQ * DIM, k_lo + z * SEQ * DIM,
                 s + z * SEQ * SEQ,
                 SEQ, DIM, scale, blockIdx.y * BM1, blockIdx.x * BN1, smem);
}

__global__ void __launch_bounds__(NTHR, 2)
gemm_qkv(const bf16* in_hi, const bf16* in_lo,
         const bf16* st_hi, const bf16* st_lo,
         const bf16* wq_hi, const bf16* wq_lo, const float* bq,
         const bf16* wk_hi, const bf16* wk_lo, const float* bk,
         const bf16* wv_hi, const bf16* wv_lo, const float* bv,
         bf16* q_hi, bf16* q_lo, bf16* k_hi, bf16* k_lo,
         bf16* v_hi, bf16* v_lo)
{
    extern __shared__ char smem[];
    const int z = blockIdx.z;
    const bf16 *Ahi, *Alo, *Bhi, *Blo;
    const float* bias;
    bf16 *Chi, *Clo;
    if (z == 0)      { Ahi = in_hi; Alo = in_lo; Bhi = wq_hi; Blo = wq_lo; bias = bq; Chi = q_hi; Clo = q_lo; }
    else if (z == 1) { Ahi = st_hi; Alo = st_lo; Bhi = wk_hi; Blo = wk_lo; bias = bk; Chi = k_hi; Clo = k_lo; }
    else             { Ahi = st_hi; Alo = st_lo; Bhi = wv_hi; Blo = wv_lo; bias = bv; Chi = v_hi; Clo = v_lo; }
    gemm_core_ms<0, 1>(Ahi, Alo, Bhi, Blo, bias, nullptr, Chi, Clo,
                       DIM, DIM, 1.f, blockIdx.y * BM2, blockIdx.x * BN2, smem);
}

__global__ void __launch_bounds__(NTHR, 2)
gemm_pv(const bf16* __restrict__ p_hi, const bf16* __restrict__ p_lo,
        const bf16* __restrict__ v_hi, const bf16* __restrict__ v_lo,
        float* __restrict__ out)
{
    extern __shared__ char smem[];
    const long z = blockIdx.z;
    gemm_core_ms<1, 0>(p_hi + z * SEQ * SEQ, p_lo + z * SEQ * SEQ,
                       v_hi + z * SEQ * DIM, v_lo + z * SEQ * DIM,
                       nullptr, out + z * SEQ * DIM, nullptr, nullptr,
                       DIM, SEQ, 1.f, blockIdx.y * BM2, blockIdx.x * BN2, smem);
}

// ------------------------------ softmax ------------------------------------
__global__ void __launch_bounds__(256)
softmax_mask(const float* __restrict__ S, const int* __restrict__ mask,
             bf16* __restrict__ Phi, bf16* __restrict__ Plo)
{
    const size_t base = (size_t)blockIdx.x * SEQ;
    const float4* rowv = (const float4*)(S + base);
    const int4*   mv   = (const int4*)(mask + base);
    const int tid = threadIdx.x;

    __shared__ float red[8];

    float v[8];
    float mx = -INFINITY;
    #pragma unroll
    for (int j = 0; j < 2; j++) {
        int idx = tid + j * 256;
        float4 sv = rowv[idx];
        int4   mm = mv[idx];
        float* vp = v + j * 4;
        vp[0] = (mm.x == 0) ? -INFINITY : sv.x;
        vp[1] = (mm.y == 0) ? -INFINITY : sv.y;
        vp[2] = (mm.z == 0) ? -INFINITY : sv.z;
        vp[3] = (mm.w == 0) ? -INFINITY : sv.w;
        mx = fmaxf(mx, fmaxf(fmaxf(vp[0], vp[1]), fmaxf(vp[2], vp[3])));
    }
    #pragma unroll
    for (int o = 16; o > 0; o >>= 1) mx = fmaxf(mx, __shfl_xor_sync(0xffffffffu, mx, o));
    if ((tid & 31) == 0) red[tid >> 5] = mx;
    __syncthreads();
    mx = red[0];
    #pragma unroll
    for (int w = 1; w < 8; w++) mx = fmaxf(mx, red[w]);
    __syncthreads();

    float sum = 0.f;
    #pragma unroll
    for (int i = 0; i < 8; i++) { v[i] = __expf(v[i] - mx); sum += v[i]; }
    #pragma unroll
    for (int o = 16; o > 0; o >>= 1) sum += __shfl_xor_sync(0xffffffffu, sum, o);
    if ((tid & 31) == 0) red[tid >> 5] = sum;
    __syncthreads();
    float total = 0.f;
    #pragma unroll
    for (int w = 0; w < 8; w++) total += red[w];

    const float inv = 1.f / total;
    #pragma unroll
    for (int j = 0; j < 2; j++) {
        int idx = tid + j * 256;
        float p0 = v[j*4+0] * inv, p1 = v[j*4+1] * inv;
        float p2 = v[j*4+2] * inv, p3 = v[j*4+3] * inv;
        bf16 h0 = __float2bfloat16(p0), h1 = __float2bfloat16(p1);
        bf16 h2 = __float2bfloat16(p2), h3 = __float2bfloat16(p3);
        bf16 l0 = __float2bfloat16(p0 - __bfloat162float(h0));
        bf16 l1 = __float2bfloat16(p1 - __bfloat162float(h1));
        bf16 l2 = __float2bfloat16(p2 - __bfloat162float(h2));
        bf16 l3 = __float2bfloat16(p3 - __bfloat162float(h3));
        __nv_bfloat162* ph = (__nv_bfloat162*)(Phi + base + idx * 4);
        __nv_bfloat162* pl = (__nv_bfloat162*)(Plo + base + idx * 4);
        ph[0] = __halves2bfloat162(h0, h1);
        ph[1] = __halves2bfloat162(h2, h3);
        pl[0] = __halves2bfloat162(l0, l1);
        pl[1] = __halves2bfloat162(l2, l3);
    }
}

// ------------------------------ launch -------------------------------------
extern "C" void kernel_launch(void* const* d_in, const int* in_sizes, int n_in,
                              void* d_out, int out_size)
{
    const float* input  = (const float*)d_in[0];
    const float* states = (const float*)d_in[1];
    const int*   mask   = (const int*)d_in[2];
    const float* wq     = (const float*)d_in[3];
    const float* bq     = (const float*)d_in[4];
    const float* wk     = (const float*)d_in[5];
    const float* bk     = (const float*)d_in[6];
    const float* wv     = (const float*)d_in[7];
    const float* bv     = (const float*)d_in[8];
    float* out = (float*)d_out;

    cudaFuncSetAttribute(gemm_scores, cudaFuncAttributeMaxDynamicSharedMemorySize, SMEM1);
    cudaFuncSetAttribute(gemm_qkv,    cudaFuncAttributeMaxDynamicSharedMemorySize, SMEM2);
    cudaFuncSetAttribute(gemm_pv,     cudaFuncAttributeMaxDynamicSharedMemorySize, SMEM2);

    bf16 *in_hi, *in_lo, *st_hi, *st_lo;
    bf16 *wq_hi, *wq_lo, *wk_hi, *wk_lo, *wv_hi, *wv_lo;
    bf16 *q_hi, *q_lo, *k_hi, *k_lo, *v_hi, *v_lo, *p_hi, *p_lo;
    float* s;
    cudaGetSymbolAddress((void**)&in_hi, g_in_hi);  cudaGetSymbolAddress((void**)&in_lo, g_in_lo);
    cudaGetSymbolAddress((void**)&st_hi, g_st_hi);  cudaGetSymbolAddress((void**)&st_lo, g_st_lo);
    cudaGetSymbolAddress((void**)&wq_hi, g_wq_hi);  cudaGetSymbolAddress((void**)&wq_lo, g_wq_lo);
    cudaGetSymbolAddress((void**)&wk_hi, g_wk_hi);  cudaGetSymbolAddress((void**)&wk_lo, g_wk_lo);
    cudaGetSymbolAddress((void**)&wv_hi, g_wv_hi);  cudaGetSymbolAddress((void**)&wv_lo, g_wv_lo);
    cudaGetSymbolAddress((void**)&q_hi,  g_q_hi);   cudaGetSymbolAddress((void**)&q_lo,  g_q_lo);
    cudaGetSymbolAddress((void**)&k_hi,  g_k_hi);   cudaGetSymbolAddress((void**)&k_lo,  g_k_lo);
    cudaGetSymbolAddress((void**)&v_hi,  g_v_hi);   cudaGetSymbolAddress((void**)&v_lo,  g_v_lo);
    cudaGetSymbolAddress((void**)&p_hi,  g_p_hi);   cudaGetSymbolAddress((void**)&p_lo,  g_p_lo);
    cudaGetSymbolAddress((void**)&s, g_s);

    const float scale = 1.0f / sqrtf((float)DIM);

    // splits (fp32 -> bf16 hi/lo)
    {
        int n4 = MTOT * DIM / 4;
        split_pair<<<dim3((n4 + 255) / 256, 2), 256>>>(
            (const float4*)input,  (__nv_bfloat162*)in_hi, (__nv_bfloat162*)in_lo,
            (const float4*)states, (__nv_bfloat162*)st_hi, (__nv_bfloat162*)st_lo, n4);
        int w4 = DIM * DIM / 4;
        split_tri<<<dim3((w4 + 255) / 256, 3), 256>>>(
            (const float4*)wq, (__nv_bfloat162*)wq_hi, (__nv_bfloat162*)wq_lo,
            (const float4*)wk, (__nv_bfloat162*)wk_hi, (__nv_bfloat162*)wk_lo,
            (const float4*)wv, (__nv_bfloat162*)wv_hi, (__nv_bfloat162*)wv_lo, w4);
    }

    // fused QKV (64x64 multistage): [16384,512] = A @ W^T + b
    gemm_qkv<<<dim3(DIM / BN2, MTOT / BM2, 3), NTHR, SMEM2>>>(
        in_hi, in_lo, st_hi, st_lo,
        wq_hi, wq_lo, bq, wk_hi, wk_lo, bk, wv_hi, wv_lo, bv,
        q_hi, q_lo, k_hi, k_lo, v_hi, v_lo);

    // scores (round-8 core): per-batch [2048,2048] = q @ k^T * scale
    gemm_scores<<<dim3(SEQ / BN1, SEQ / BM1, BATCH), NTHR, SMEM1>>>(
        q_hi, q_lo, k_hi, k_lo, s, scale);

    // masked softmax -> P hi/lo bf16
    softmax_mask<<<BATCH * SEQ, 256>>>(s, mask, p_hi, p_lo);

    // context (64x64 multistage): per-batch [2048,512] = P @ V
    gemm_pv<<<dim3(DIM / BN2, SEQ / BM2, BATCH), NTHR, SMEM2>>>(
        p_hi, p_lo, v_hi, v_lo, out);
}

// round 13
// speedup vs baseline: 1.1167x; 1.0540x over previous
#include <cuda_runtime.h>
#include <cuda_bf16.h>
#include <cstdint>
#include <math.h>

// ---------------------------------------------------------------------------
// Attention B=8, L=2048, D=512 fp32 — bf16-split (3x mma.sync) HMMA pipeline.
// Round 13: exact round-8 config (best: 794.6us) + k-phase offset: odd-parity
// blocks start the K loop at chunk nch/2, dephasing co-resident CTAs so one
// CTA's barrier/ldsm window hides behind the other's MMA burst.
// 256-thr CTAs, 2 CTAs/SM, tile 128x64, warp 32x32, 2-stage cp.async KC=64.
// ---------------------------------------------------------------------------

#define BATCH 8
#define SEQ   2048
#define DIM   512
#define MTOT  (BATCH*SEQ)

#define BM   128
#define BN   64
#define KC   64
#define NTHR 256

typedef __nv_bfloat16 bf16;

#define A_B   (BM*128)            // 16384 (128 rows x 64 bf16)
#define B_B   (BN*128)            // 8192  (64 rows x 64 bf16)
#define STAGE (2*A_B + 2*B_B)     // 49152
#define SMEM_TOTAL (2*STAGE)      // 98304 -> 2 CTAs/SM = 192KB

// ------------------------------ scratch ------------------------------------
__device__ bf16 g_in_hi[MTOT*DIM], g_in_lo[MTOT*DIM];
__device__ bf16 g_st_hi[MTOT*DIM], g_st_lo[MTOT*DIM];
__device__ bf16 g_wq_hi[DIM*DIM], g_wq_lo[DIM*DIM];
__device__ bf16 g_wk_hi[DIM*DIM], g_wk_lo[DIM*DIM];
__device__ bf16 g_wv_hi[DIM*DIM], g_wv_lo[DIM*DIM];
__device__ bf16 g_q_hi[MTOT*DIM], g_q_lo[MTOT*DIM];
__device__ bf16 g_k_hi[MTOT*DIM], g_k_lo[MTOT*DIM];
__device__ bf16 g_v_hi[MTOT*DIM], g_v_lo[MTOT*DIM];
__device__ float g_s[(size_t)BATCH*SEQ*SEQ];
__device__ bf16 g_p_hi[(size_t)BATCH*SEQ*SEQ], g_p_lo[(size_t)BATCH*SEQ*SEQ];

// ------------------------------ helpers ------------------------------------
__device__ __forceinline__ uint32_t smem_u32(const void* p) {
    uint32_t a;
    asm("{ .reg .u64 t; cvta.to.shared.u64 t, %1; cvt.u32.u64 %0, t; }" : "=r"(a) : "l"(p));
    return a;
}
#define SW128(o) ((o) ^ (((o) >> 3) & 0x70))

__device__ __forceinline__ void cp16(uint32_t dst, const void* src) {
    asm volatile("cp.async.cg.shared.global [%0], [%1], 16;"
                 :: "r"(dst), "l"(__cvta_generic_to_global(src)) : "memory");
}
#define CP_COMMIT() asm volatile("cp.async.commit_group;" ::: "memory")

__device__ __forceinline__ void ldsm4(uint32_t* r, uint32_t addr) {
    asm volatile("ldmatrix.sync.aligned.m8n8.x4.shared.b16 {%0,%1,%2,%3}, [%4];"
                 : "=r"(r[0]), "=r"(r[1]), "=r"(r[2]), "=r"(r[3]) : "r"(addr));
}
__device__ __forceinline__ void ldsm4t(uint32_t* r, uint32_t addr) {
    asm volatile("ldmatrix.sync.aligned.m8n8.x4.trans.shared.b16 {%0,%1,%2,%3}, [%4];"
                 : "=r"(r[0]), "=r"(r[1]), "=r"(r[2]), "=r"(r[3]) : "r"(addr));
}
__device__ __forceinline__ void mma16816(float* c, const uint32_t* a,
                                         uint32_t b0, uint32_t b1) {
    asm volatile("mma.sync.aligned.m16n8k16.row.col.f32.bf16.bf16.f32 "
                 "{%0,%1,%2,%3}, {%4,%5,%6,%7}, {%8,%9}, {%0,%1,%2,%3};"
                 : "+f"(c[0]), "+f"(c[1]), "+f"(c[2]), "+f"(c[3])
                 : "r"(a[0]), "r"(a[1]), "r"(a[2]), "r"(a[3]), "r"(b0), "r"(b1));
}

// ------------------------------ split kernels ------------------------------
__device__ __forceinline__ void split4(const float4* src, __nv_bfloat162* hi,
                                       __nv_bfloat162* lo, int i) {
    float4 v = src[i];
    bf16 h0 = __float2bfloat16(v.x), h1 = __float2bfloat16(v.y);
    bf16 h2 = __float2bfloat16(v.z), h3 = __float2bfloat16(v.w);
    bf16 l0 = __float2bfloat16(v.x - __bfloat162float(h0));
    bf16 l1 = __float2bfloat16(v.y - __bfloat162float(h1));
    bf16 l2 = __float2bfloat16(v.z - __bfloat162float(h2));
    bf16 l3 = __float2bfloat16(v.w - __bfloat162float(h3));
    hi[2*i]   = __halves2bfloat162(h0, h1);
    hi[2*i+1] = __halves2bfloat162(h2, h3);
    lo[2*i]   = __halves2bfloat162(l0, l1);
    lo[2*i+1] = __halves2bfloat162(l2, l3);
}

__global__ void __launch_bounds__(256)
split_pair(const float4* s0, __nv_bfloat162* h0, __nv_bfloat162* l0,
           const float4* s1, __nv_bfloat162* h1, __nv_bfloat162* l1, int n4)
{
    int i = blockIdx.x * 256 + threadIdx.x;
    if (i >= n4) return;
    if (blockIdx.y == 0) split4(s0, h0, l0, i);
    else                 split4(s1, h1, l1, i);
}

__global__ void __launch_bounds__(256)
split_tri(const float4* s0, __nv_bfloat162* h0, __nv_bfloat162* l0,
          const float4* s1, __nv_bfloat162* h1, __nv_bfloat162* l1,
          const float4* s2, __nv_bfloat162* h2, __nv_bfloat162* l2, int n4)
{
    int i = blockIdx.x * 256 + threadIdx.x;
    if (i >= n4) return;
    if (blockIdx.y == 0)      split4(s0, h0, l0, i);
    else if (blockIdx.y == 1) split4(s1, h1, l1, i);
    else                      split4(s2, h2, l2, i);
}

// ------------------------------ GEMM core ----------------------------------
// 256 threads, 8 warps (4m x 2n), block tile 128x64, warp tile 32x32.
// C[M,N] = scale*(A @ Bop) (+bias). A = Ahi+Alo [M,K] K-major bf16.
// BMODE 0: B is [N,K] K-major. BMODE 1: B is [K,N] N-major (trans ldmatrix).
// EPI 0: fp32*scale. EPI 1: +bias, split bf16 hi/lo.
// koff: K-chunk phase offset (in chunks) to dephase co-resident CTAs.
template <int BMODE, int EPI>
__device__ __forceinline__ void gemm_core(
    const bf16* __restrict__ Ahi, const bf16* __restrict__ Alo,
    const bf16* __restrict__ Bhi, const bf16* __restrict__ Blo,
    const float* __restrict__ bias,
    float* __restrict__ Cf, bf16* __restrict__ Chi, bf16* __restrict__ Clo,
    int N, int K, float scale, int m0, int n0, int koff, char* smem)
{
    const uint32_t sb = smem_u32(smem);
    const int tid = threadIdx.x, lane = tid & 31, wid = tid >> 5;
    const int wm = wid & 3, wn = wid >> 2;    // 4(m) x 2(n)
    const int ldB = BMODE ? N : K;
    const int nch = K / KC;

    auto issue = [&](int j) {
        int chunk = j + koff;
        if (chunk >= nch) chunk -= nch;
        const int k0 = chunk * KC;
        const uint32_t st = sb + (j & 1) * STAGE;
        // A hi/lo: 128 rows x 64 bf16 (8 x 16B chunks per row)
        #pragma unroll
        for (int u = 0; u < 4; u++) {
            int idx = tid + u * NTHR;          // 0..1023
            int r = idx >> 3, c = idx & 7;
            uint32_t off = SW128((uint32_t)(r * 128 + c * 16));
            cp16(st + off,       Ahi + (long)(m0 + r) * K + k0 + c * 8);
            cp16(st + A_B + off, Alo + (long)(m0 + r) * K + k0 + c * 8);
        }
        const uint32_t bst = st + 2 * A_B;
        if (BMODE == 0) {
            // B: 64 rows (n) x 64 bf16 (k)
            #pragma unroll
            for (int u = 0; u < 2; u++) {
                int idx = tid + u * NTHR;      // 0..511
                int r = idx >> 3, c = idx & 7;
                uint32_t off = SW128((uint32_t)(r * 128 + c * 16));
                cp16(bst + off,       Bhi + (long)(n0 + r) * ldB + k0 + c * 8);
                cp16(bst + B_B + off, Blo + (long)(n0 + r) * ldB + k0 + c * 8);
            }
        } else {
            // B: 64 rows (k) x 64 bf16 (n)
            #pragma unroll
            for (int u = 0; u < 2; u++) {
                int idx = tid + u * NTHR;
                int kk = idx >> 3, nc = idx & 7;
                uint32_t off = SW128((uint32_t)(kk * 128 + nc * 16));
                cp16(bst + off,       Bhi + (long)(k0 + kk) * ldB + n0 + nc * 8);
                cp16(bst + B_B + off, Blo + (long)(k0 + kk) * ldB + n0 + nc * 8);
            }
        }
        CP_COMMIT();
    };

    float acc[2][4][4];
    #pragma unroll
    for (int a = 0; a < 2; a++)
        #pragma unroll
        for (int b = 0; b < 4; b++)
            #pragma unroll
            for (int c = 0; c < 4; c++) acc[a][b][c] = 0.f;

    issue(0); issue(1);

    for (int i = 0; i < nch; i++) {
        if (i < nch - 1) asm volatile("cp.async.wait_group 1;" ::: "memory");
        else             asm volatile("cp.async.wait_group 0;" ::: "memory");
        __syncthreads();

        const uint32_t st = sb + (i & 1) * STAGE;
        const uint32_t sAhi = st, sAlo = st + A_B;
        const uint32_t sBhi = st + 2 * A_B, sBlo = st + 2 * A_B + B_B;

        #pragma unroll
        for (int ks = 0; ks < 4; ks++) {
            uint32_t ah[2][4], al[2][4];
            #pragma unroll
            for (int mc = 0; mc < 2; mc++) {
                int row = wm * 32 + mc * 16 + (lane & 15);
                int kb  = ks * 32 + (lane >> 4) * 16;
                uint32_t off = SW128((uint32_t)(row * 128 + kb));
                ldsm4(ah[mc], sAhi + off);
                ldsm4(al[mc], sAlo + off);
            }
            #pragma unroll
            for (int p = 0; p < 2; p++) {
                uint32_t bh[4], bl[4];
                if (BMODE == 0) {
                    int row = wn * 32 + p * 16 + ((lane >> 4) & 1) * 8 + (lane & 7);
                    int kb  = ks * 32 + ((lane >> 3) & 1) * 16;
                    uint32_t off = SW128((uint32_t)(row * 128 + kb));
                    ldsm4(bh, sBhi + off);
                    ldsm4(bl, sBlo + off);
                } else {
                    int kk   = ks * 16 + ((lane >> 3) & 1) * 8 + (lane & 7);
                    int ncol = wn * 32 + p * 16 + ((lane >> 4) & 1) * 8;
                    uint32_t off = SW128((uint32_t)(kk * 128 + ncol * 2));
                    ldsm4t(bh, sBhi + off);
                    ldsm4t(bl, sBlo + off);
                }
                #pragma unroll
                for (int mc = 0; mc < 2; mc++)
                    #pragma unroll
                    for (int s = 0; s < 2; s++) {
                        float* a = acc[mc][p * 2 + s];
                        mma16816(a, ah[mc], bh[s*2], bh[s*2+1]);   // hi*hi
                        mma16816(a, ah[mc], bl[s*2], bl[s*2+1]);   // hi*lo
                        mma16816(a, al[mc], bh[s*2], bh[s*2+1]);   // lo*hi
                    }
            }
        }
        __syncthreads();
        if (i + 2 < nch) issue(i + 2);
    }

    // ---- epilogue: warp covers rows wm*32..+31, cols wn*32..+31 ----
    const int g = lane >> 2, tig = lane & 3;
    #pragma unroll
    for (int mc = 0; mc < 2; mc++) {
        int row = m0 + wm * 32 + mc * 16 + g;
        #pragma unroll
        for (int ng = 0; ng < 4; ng++) {
            int col = n0 + wn * 32 + ng * 8 + tig * 2;
            float c0 = acc[mc][ng][0], c1 = acc[mc][ng][1];
            float c2 = acc[mc][ng][2], c3 = acc[mc][ng][3];
            if (EPI == 0) {
                *(float2*)(Cf + (long)row * N + col)       = make_float2(c0 * scale, c1 * scale);
                *(float2*)(Cf + (long)(row + 8) * N + col) = make_float2(c2 * scale, c3 * scale);
            } else {
                float b0 = bias[col], b1 = bias[col + 1];
                float v0 = c0 + b0, v1 = c1 + b1;
                float v2 = c2 + b0, v3 = c3 + b1;
                bf16 h0 = __float2bfloat16(v0), h1 = __float2bfloat16(v1);
                bf16 h2 = __float2bfloat16(v2), h3 = __float2bfloat16(v3);
                bf16 l0 = __float2bfloat16(v0 - __bfloat162float(h0));
                bf16 l1 = __float2bfloat16(v1 - __bfloat162float(h1));
                bf16 l2 = __float2bfloat16(v2 - __bfloat162float(h2));
                bf16 l3 = __float2bfloat16(v3 - __bfloat162float(h3));
                long o0 = (long)row * N + col, o1 = (long)(row + 8) * N + col;
                *(__nv_bfloat162*)(Chi + o0) = __halves2bfloat162(h0, h1);
                *(__nv_bfloat162*)(Chi + o1) = __halves2bfloat162(h2, h3);
                *(__nv_bfloat162*)(Clo + o0) = __halves2bfloat162(l0, l1);
                *(__nv_bfloat162*)(Clo + o1) = __halves2bfloat162(l2, l3);
            }
        }
    }
}

// ---- fused QKV: blockIdx.z selects projection ----
__global__ void __launch_bounds__(NTHR, 2)
gemm_qkv(const bf16* in_hi, const bf16* in_lo,
         const bf16* st_hi, const bf16* st_lo,
         const bf16* wq_hi, const bf16* wq_lo, const float* bq,
         const bf16* wk_hi, const bf16* wk_lo, const float* bk,
         const bf16* wv_hi, const bf16* wv_lo, const float* bv,
         bf16* q_hi, bf16* q_lo, bf16* k_hi, bf16* k_lo,
         bf16* v_hi, bf16* v_lo)
{
    extern __shared__ char smem[];
    const int z = blockIdx.z;
    const bf16 *Ahi, *Alo, *Bhi, *Blo;
    const float* bias;
    bf16 *Chi, *Clo;
    if (z == 0)      { Ahi = in_hi; Alo = in_lo; Bhi = wq_hi; Blo = wq_lo; bias = bq; Chi = q_hi; Clo = q_lo; }
    else if (z == 1) { Ahi = st_hi; Alo = st_lo; Bhi = wk_hi; Blo = wk_lo; bias = bk; Chi = k_hi; Clo = k_lo; }
    else             { Ahi = st_hi; Alo = st_lo; Bhi = wv_hi; Blo = wv_lo; bias = bv; Chi = v_hi; Clo = v_lo; }
    const int koff = ((blockIdx.x + blockIdx.y + blockIdx.z) & 1) * ((DIM / KC) / 2);
    gemm_core<0, 1>(Ahi, Alo, Bhi, Blo, bias, nullptr, Chi, Clo,
                    DIM, DIM, 1.f, blockIdx.y * BM, blockIdx.x * BN, koff, smem);
}

// ---- batched GEMM (scores / PV), blockIdx.z = batch ----
template <int BMODE>
__global__ void __launch_bounds__(NTHR, 2)
gemm_batch(const bf16* __restrict__ Ahi_, const bf16* __restrict__ Alo_,
           const bf16* __restrict__ Bhi_, const bf16* __restrict__ Blo_,
           float* __restrict__ Cf, int N, int K,
           long sA, long sB, long sC, float scale)
{
    extern __shared__ char smem[];
    const int z = blockIdx.z;
    const int koff = ((blockIdx.x + blockIdx.y + blockIdx.z) & 1) * ((K / KC) / 2);
    gemm_core<BMODE, 0>(Ahi_ + (long)z * sA, Alo_ + (long)z * sA,
                        Bhi_ + (long)z * sB, Blo_ + (long)z * sB,
                        nullptr, Cf + (long)z * sC, nullptr, nullptr,
                        N, K, scale, blockIdx.y * BM, blockIdx.x * BN, koff, smem);
}

// ------------------------------ softmax ------------------------------------
__global__ void __launch_bounds__(256)
softmax_mask(const float* __restrict__ S, const int* __restrict__ mask,
             bf16* __restrict__ Phi, bf16* __restrict__ Plo)
{
    const size_t base = (size_t)blockIdx.x * SEQ;
    const float4* rowv = (const float4*)(S + base);
    const int4*   mv   = (const int4*)(mask + base);
    const int tid = threadIdx.x;

    __shared__ float red[8];

    float v[8];
    float mx = -INFINITY;
    #pragma unroll
    for (int j = 0; j < 2; j++) {
        int idx = tid + j * 256;
        float4 sv = rowv[idx];
        int4   mm = mv[idx];
        float* vp = v + j * 4;
        vp[0] = (mm.x == 0) ? -INFINITY : sv.x;
        vp[1] = (mm.y == 0) ? -INFINITY : sv.y;
        vp[2] = (mm.z == 0) ? -INFINITY : sv.z;
        vp[3] = (mm.w == 0) ? -INFINITY : sv.w;
        mx = fmaxf(mx, fmaxf(fmaxf(vp[0], vp[1]), fmaxf(vp[2], vp[3])));
    }
    #pragma unroll
    for (int o = 16; o > 0; o >>= 1) mx = fmaxf(mx, __shfl_xor_sync(0xffffffffu, mx, o));
    if ((tid & 31) == 0) red[tid >> 5] = mx;
    __syncthreads();
    mx = red[0];
    #pragma unroll
    for (int w = 1; w < 8; w++) mx = fmaxf(mx, red[w]);
    __syncthreads();

    float sum = 0.f;
    #pragma unroll
    for (int i = 0; i < 8; i++) { v[i] = __expf(v[i] - mx); sum += v[i]; }
    #pragma unroll
    for (int o = 16; o > 0; o >>= 1) sum += __shfl_xor_sync(0xffffffffu, sum, o);
    if ((tid & 31) == 0) red[tid >> 5] = sum;
    __syncthreads();
    float total = 0.f;
    #pragma unroll
    for (int w = 0; w < 8; w++) total += red[w];

    const float inv = 1.f / total;
    #pragma unroll
    for (int j = 0; j < 2; j++) {
        int idx = tid + j * 256;
        float p0 = v[j*4+0] * inv, p1 = v[j*4+1] * inv;
        float p2 = v[j*4+2] * inv, p3 = v[j*4+3] * inv;
        bf16 h0 = __float2bfloat16(p0), h1 = __float2bfloat16(p1);
        bf16 h2 = __float2bfloat16(p2), h3 = __float2bfloat16(p3);
        bf16 l0 = __float2bfloat16(p0 - __bfloat162float(h0));
        bf16 l1 = __float2bfloat16(p1 - __bfloat162float(h1));
        bf16 l2 = __float2bfloat16(p2 - __bfloat162float(h2));
        bf16 l3 = __float2bfloat16(p3 - __bfloat162float(h3));
        __nv_bfloat162* ph = (__nv_bfloat162*)(Phi + base + idx * 4);
        __nv_bfloat162* pl = (__nv_bfloat162*)(Plo + base + idx * 4);
        ph[0] = __halves2bfloat162(h0, h1);
        ph[1] = __halves2bfloat162(h2, h3);
        pl[0] = __halves2bfloat162(l0, l1);
        pl[1] = __halves2bfloat162(l2, l3);
    }
}

// ------------------------------ launch -------------------------------------
extern "C" void kernel_launch(void* const* d_in, const int* in_sizes, int n_in,
                              void* d_out, int out_size)
{
    const float* input  = (const float*)d_in[0];
    const float* states = (const float*)d_in[1];
    const int*   mask   = (const int*)d_in[2];
    const float* wq     = (const float*)d_in[3];
    const float* bq     = (const float*)d_in[4];
    const float* wk     = (const float*)d_in[5];
    const float* bk     = (const float*)d_in[6];
    const float* wv     = (const float*)d_in[7];
    const float* bv     = (const float*)d_in[8];
    float* out = (float*)d_out;

    cudaFuncSetAttribute(gemm_qkv,      cudaFuncAttributeMaxDynamicSharedMemorySize, SMEM_TOTAL);
    cudaFuncSetAttribute(gemm_batch<0>, cudaFuncAttributeMaxDynamicSharedMemorySize, SMEM_TOTAL);
    cudaFuncSetAttribute(gemm_batch<1>, cudaFuncAttributeMaxDynamicSharedMemorySize, SMEM_TOTAL);

    bf16 *in_hi, *in_lo, *st_hi, *st_lo;
    bf16 *wq_hi, *wq_lo, *wk_hi, *wk_lo, *wv_hi, *wv_lo;
    bf16 *q_hi, *q_lo, *k_hi, *k_lo, *v_hi, *v_lo, *p_hi, *p_lo;
    float* s;
    cudaGetSymbolAddress((void**)&in_hi, g_in_hi);  cudaGetSymbolAddress((void**)&in_lo, g_in_lo);
    cudaGetSymbolAddress((void**)&st_hi, g_st_hi);  cudaGetSymbolAddress((void**)&st_lo, g_st_lo);
    cudaGetSymbolAddress((void**)&wq_hi, g_wq_hi);  cudaGetSymbolAddress((void**)&wq_lo, g_wq_lo);
    cudaGetSymbolAddress((void**)&wk_hi, g_wk_hi);  cudaGetSymbolAddress((void**)&wk_lo, g_wk_lo);
    cudaGetSymbolAddress((void**)&wv_hi, g_wv_hi);  cudaGetSymbolAddress((void**)&wv_lo, g_wv_lo);
    cudaGetSymbolAddress((void**)&q_hi,  g_q_hi);   cudaGetSymbolAddress((void**)&q_lo,  g_q_lo);
    cudaGetSymbolAddress((void**)&k_hi,  g_k_hi);   cudaGetSymbolAddress((void**)&k_lo,  g_k_lo);
    cudaGetSymbolAddress((void**)&v_hi,  g_v_hi);   cudaGetSymbolAddress((void**)&v_lo,  g_v_lo);
    cudaGetSymbolAddress((void**)&p_hi,  g_p_hi);   cudaGetSymbolAddress((void**)&p_lo,  g_p_lo);
    cudaGetSymbolAddress((void**)&s, g_s);

    const float scale = 1.0f / sqrtf((float)DIM);
    const long sQK = (long)SEQ * DIM;
    const long sS  = (long)SEQ * SEQ;

    // splits (fp32 -> bf16 hi/lo)
    {
        int n4 = MTOT * DIM / 4;
        split_pair<<<dim3((n4 + 255) / 256, 2), 256>>>(
            (const float4*)input,  (__nv_bfloat162*)in_hi, (__nv_bfloat162*)in_lo,
            (const float4*)states, (__nv_bfloat162*)st_hi, (__nv_bfloat162*)st_lo, n4);
        int w4 = DIM * DIM / 4;
        split_tri<<<dim3((w4 + 255) / 256, 3), 256>>>(
            (const float4*)wq, (__nv_bfloat162*)wq_hi, (__nv_bfloat162*)wq_lo,
            (const float4*)wk, (__nv_bfloat162*)wk_hi, (__nv_bfloat162*)wk_lo,
            (const float4*)wv, (__nv_bfloat162*)wv_hi, (__nv_bfloat162*)wv_lo, w4);
    }

    // fused QKV: [16384,512] = A @ W^T + b, z = projection
    gemm_qkv<<<dim3(DIM / BN, MTOT / BM, 3), NTHR, SMEM_TOTAL>>>(
        in_hi, in_lo, st_hi, st_lo,
        wq_hi, wq_lo, bq, wk_hi, wk_lo, bk, wv_hi, wv_lo, bv,
        q_hi, q_lo, k_hi, k_lo, v_hi, v_lo);

    // scores: per-batch [2048,2048] = q @ k^T * scale
    gemm_batch<0><<<dim3(SEQ / BN, SEQ / BM, BATCH), NTHR, SMEM_TOTAL>>>(
        q_hi, q_lo, k_hi, k_lo, s, SEQ, DIM, sQK, sQK, sS, scale);

    // masked softmax -> P hi/lo bf16
    softmax_mask<<<BATCH * SEQ, 256>>>(s, mask, p_hi, p_lo);

    // context: per-batch [2048,512] = P @ V  (V [2048,512] N-major, trans)
    gemm_batch<1><<<dim3(DIM / BN, SEQ / BM, BATCH), NTHR, SMEM_TOTAL>>>(
        p_hi, p_lo, v_hi, v_lo, out, DIM, SEQ, sS, sQK, sQK, 1.f);
}